// round 7
// baseline (speedup 1.0000x reference)
#include <cuda_runtime.h>
#include <cuda_bf16.h>
#include <math.h>
#include <stdint.h>

// ----------------------------------------------------------------------------
// MultiScaleDecoder, tensor-core version (mma.sync bf16, fp32 accum).
//   prepass: inputs fp32 -> bf16 (one [49152,512] A matrix), weights -> bf16
//   L1: relu(A @ Wd^T)  M=49152 N=512 K=512 -> scatter X1[65536,384] bf16
//   L2: relu(X1 @ w1^T) M=65536 N=256 K=384 -> scatter X2[262144,64] bf16
//   L3: relu(X2 @ w2^T) M=262144 N=128 K=64 -> scatter X3[1048576,32] bf16
//   L4: sigmoid head, smem-staged coalesced output (ostage MUST be 16B-aligned)
// ----------------------------------------------------------------------------

#define NP 16384
#define L1_M (3 * NP)                 // 49152
#define X1_ROWS (NP * 4)              // 65536
#define X2_ROWS (NP * 16)             // 262144
#define X3_ROWS (NP * 64)             // 1048576

__device__ __align__(256) __nv_bfloat16 g_Ain[(size_t)L1_M * 512];    // 50.3 MB
__device__ __align__(256) __nv_bfloat16 g_X1[(size_t)X1_ROWS * 384];  // 50.3 MB
__device__ __align__(256) __nv_bfloat16 g_X2[(size_t)X2_ROWS * 64];   // 33.6 MB
__device__ __align__(256) __nv_bfloat16 g_X3[(size_t)X3_ROWS * 32];   // 67.1 MB
__device__ __align__(256) __nv_bfloat16 g_Wd[512 * 512];              // [n][k]
__device__ __align__(256) __nv_bfloat16 g_W1[256 * 384];              // [n][k]
__device__ __align__(256) __nv_bfloat16 g_W2[128 * 64];               // [n][k]

// ---------------------------------------------------------------- prepasses
__global__ __launch_bounds__(256) void f2bf(const float* __restrict__ src,
                                            __nv_bfloat16* __restrict__ dst,
                                            int n) {
    int i = (blockIdx.x * 256 + threadIdx.x) * 4;
    if (i < n) {
        float4 v = *reinterpret_cast<const float4*>(src + i);
        *reinterpret_cast<__nv_bfloat162*>(dst + i)     = __floats2bfloat162_rn(v.x, v.y);
        *reinterpret_cast<__nv_bfloat162*>(dst + i + 2) = __floats2bfloat162_rn(v.z, v.w);
    }
}

// dense_w [k=512][n=512] -> g_Wd [n][k] bf16
__global__ void transpose_w(const float* __restrict__ src,
                            __nv_bfloat16* __restrict__ dst) {
    __shared__ float t[32][33];
    int k0 = blockIdx.y * 32, n0 = blockIdx.x * 32;
    int tx = threadIdx.x, ty = threadIdx.y;  // block (32, 8)
    for (int r = ty; r < 32; r += 8) t[r][tx] = src[(k0 + r) * 512 + n0 + tx];
    __syncthreads();
    for (int r = ty; r < 32; r += 8)
        dst[(size_t)(n0 + r) * 512 + k0 + tx] = __float2bfloat16(t[tx][r]);
}

// ---------------------------------------------------------------- mma utils
__device__ __forceinline__ uint32_t smem_u32(const void* p) {
    return (uint32_t)__cvta_generic_to_shared(p);
}
__device__ __forceinline__ void ldsm4(uint32_t& r0, uint32_t& r1, uint32_t& r2,
                                      uint32_t& r3, uint32_t addr) {
    asm volatile("ldmatrix.sync.aligned.m8n8.x4.shared.b16 {%0,%1,%2,%3}, [%4];\n"
                 : "=r"(r0), "=r"(r1), "=r"(r2), "=r"(r3) : "r"(addr));
}
__device__ __forceinline__ void mma16816(float* c, const uint32_t* a,
                                         const uint32_t* b) {
    asm volatile(
        "mma.sync.aligned.m16n8k16.row.col.f32.bf16.bf16.f32 "
        "{%0,%1,%2,%3}, {%4,%5,%6,%7}, {%8,%9}, {%0,%1,%2,%3};\n"
        : "+f"(c[0]), "+f"(c[1]), "+f"(c[2]), "+f"(c[3])
        : "r"(a[0]), "r"(a[1]), "r"(a[2]), "r"(a[3]), "r"(b[0]), "r"(b[1]));
}
__device__ __forceinline__ void cp16(void* sdst, const void* gsrc) {
    asm volatile("cp.async.cg.shared.global [%0], [%1], 16;\n" ::
                 "r"(smem_u32(sdst)), "l"(gsrc));
}

#define BM 128
#define BN 128
#define BK 64
#define LDP 72   // 144B row stride: each 8-row ldmatrix phase hits distinct banks
#define STAGE_ELEMS (BM * LDP)            // 9216 bf16 per matrix per stage
#define SMEM_BYTES (4 * STAGE_ELEMS * 2)  // A/B x 2 stages = 73728 B

// ---------------------------------------------------------------- GEMM + scatter
// EPI: 1 = dense->X1 scatter, 2 = deconv1->X2 scatter, 3 = deconv2->X3 scatter
template <int EPI>
__global__ __launch_bounds__(256)
void mma_gemm(const __nv_bfloat16* __restrict__ A,
              const __nv_bfloat16* __restrict__ B,
              const float* __restrict__ bias,
              __nv_bfloat16* __restrict__ Out, int M, int N, int K)
{
    extern __shared__ __align__(16) __nv_bfloat16 sdyn[];
    __nv_bfloat16* As = sdyn;                       // [2][STAGE_ELEMS]
    __nv_bfloat16* Bs = sdyn + 2 * STAGE_ELEMS;     // [2][STAGE_ELEMS]

    const int tid = threadIdx.x;
    const int warp = tid >> 5, lane = tid & 31;
    const int row0 = blockIdx.y * BM;
    const int col0 = blockIdx.x * BN;
    const int wm = (warp >> 2) * 64;   // warp tile 64x32
    const int wn = (warp & 3) * 32;

    const int NIT = K / BK;

    auto load_stage = [&](int buf, int ko) {
        #pragma unroll
        for (int c = 0; c < 4; c++) {
            int ch = tid + c * 256;            // 0..1023
            int r = ch >> 3, cc = (ch & 7) * 8;
            cp16(&As[buf * STAGE_ELEMS + r * LDP + cc],
                 &A[(size_t)(row0 + r) * K + ko + cc]);
        }
        #pragma unroll
        for (int c = 0; c < 4; c++) {
            int ch = tid + c * 256;
            int r = ch >> 3, cc = (ch & 7) * 8;
            cp16(&Bs[buf * STAGE_ELEMS + r * LDP + cc],
                 &B[(size_t)(col0 + r) * K + ko + cc]);
        }
        asm volatile("cp.async.commit_group;\n");
    };

    float acc[4][4][4];
    #pragma unroll
    for (int i = 0; i < 4; i++)
        #pragma unroll
        for (int j = 0; j < 4; j++)
            #pragma unroll
            for (int q = 0; q < 4; q++) acc[i][j][q] = 0.f;

    load_stage(0, 0);

    for (int it = 0; it < NIT; it++) {
        if (it + 1 < NIT) {
            load_stage((it + 1) & 1, (it + 1) * BK);
            asm volatile("cp.async.wait_group 1;\n");
        } else {
            asm volatile("cp.async.wait_group 0;\n");
        }
        __syncthreads();

        const int sb = it & 1;
        #pragma unroll
        for (int ks = 0; ks < 4; ks++) {
            const int k0 = ks * 16;
            uint32_t a[4][4], b[4][2];
            #pragma unroll
            for (int i = 0; i < 4; i++) {
                int r = wm + i * 16 + (lane & 15);
                int kk = k0 + ((lane >> 4) << 3);
                ldsm4(a[i][0], a[i][1], a[i][2], a[i][3],
                      smem_u32(&As[sb * STAGE_ELEMS + r * LDP + kk]));
            }
            #pragma unroll
            for (int jp = 0; jp < 2; jp++) {
                int rB = wn + jp * 16 + ((lane >> 4) << 3) + (lane & 7);
                int kk = k0 + (((lane >> 3) & 1) << 3);
                ldsm4(b[2 * jp][0], b[2 * jp][1], b[2 * jp + 1][0], b[2 * jp + 1][1],
                      smem_u32(&Bs[sb * STAGE_ELEMS + rB * LDP + kk]));
            }
            #pragma unroll
            for (int i = 0; i < 4; i++)
                #pragma unroll
                for (int j = 0; j < 4; j++) mma16816(acc[i][j], a[i], b[j]);
        }
        __syncthreads();
    }

    // epilogue: bias + relu + scatter, bf162 pair stores
    auto epi_store = [&](int row, int col, float v0, float v1) {
        float b0, b1;
        if (EPI == 1)      { b0 = bias[col];      b1 = bias[col + 1]; }
        else if (EPI == 2) { b0 = bias[col & 63]; b1 = bias[(col & 63) + 1]; }
        else               { b0 = bias[col & 31]; b1 = bias[(col & 31) + 1]; }
        v0 = fmaxf(v0 + b0, 0.f);
        v1 = fmaxf(v1 + b1, 0.f);
        size_t addr;
        if (EPI == 1) {
            const int pos = col >> 7, kc = col & 127;
            const int s = row >> 14, nl = row & (NP - 1);
            addr = ((size_t)(nl * 4 + pos)) * 384 + s * 128 + kc;
        } else if (EPI == 2) {
            const int a_ = col >> 7, c_ = (col >> 6) & 1, f = col & 63;
            const int nn = row >> 2, ii = (row >> 1) & 1, jj = row & 1;
            addr = ((size_t)(nn * 16 + (2 * ii + a_) * 4 + (2 * jj + c_))) * 64 + f;
        } else {
            const int a_ = col >> 6, c_ = (col >> 5) & 1, f = col & 31;
            const int nn = row >> 4, p = (row >> 2) & 3, q = row & 3;
            addr = ((size_t)(nn * 64 + (2 * p + a_) * 8 + (2 * q + c_))) * 32 + f;
        }
        *reinterpret_cast<__nv_bfloat162*>(&Out[addr]) = __floats2bfloat162_rn(v0, v1);
    };

    #pragma unroll
    for (int i = 0; i < 4; i++) {
        const int mA = row0 + wm + i * 16 + (lane >> 2);
        #pragma unroll
        for (int j = 0; j < 4; j++) {
            const int nA = col0 + wn + j * 8 + 2 * (lane & 3);
            epi_store(mA,     nA, acc[i][j][0], acc[i][j][1]);
            epi_store(mA + 8, nA, acc[i][j][2], acc[i][j][3]);
        }
    }
}

// ----------------------------------------------------------------------------
// Layer 4 standalone, smem-staged coalesced output.
// Block = 8 patches = 512 X3 rows; 256 threads, 2 rows/thread.
// ostage is accessed as float4 -> MUST be 16B-aligned (R5/R6 fault was here).
// ----------------------------------------------------------------------------
__global__ __launch_bounds__(256)
void layer4_kernel(const __nv_bfloat16* __restrict__ X3,
                   const float* __restrict__ w3, const float* __restrict__ b3,
                   float* __restrict__ out)
{
    __shared__ __align__(16) float ostage[6144];   // 24 KB, float4-accessed
    __shared__ float ws[384];
    __shared__ float bsm[3];

    const int tid = threadIdx.x;
    for (int i = tid; i < 384; i += 256) ws[i] = w3[i];
    if (tid < 3) bsm[tid] = b3[tid];
    __syncthreads();

    const int r0 = blockIdx.x * 512;

    #pragma unroll
    for (int h = 0; h < 2; h++) {
        const int rl = tid + h * 256;            // local row 0..511
        const int r  = r0 + rl;
        // coalesced 64B row read
        uint4 xr[4];
        const uint4* xp = reinterpret_cast<const uint4*>(X3 + (size_t)r * 32);
        #pragma unroll
        for (int i = 0; i < 4; i++) xr[i] = xp[i];
        float x[32];
        #pragma unroll
        for (int i = 0; i < 16; i++) {
            __nv_bfloat162 pr = reinterpret_cast<const __nv_bfloat162*>(xr)[i];
            float2 f2 = __bfloat1622float2(pr);
            x[2 * i] = f2.x; x[2 * i + 1] = f2.y;
        }
        const int nl = rl >> 6, P = (rl >> 3) & 7, Q = rl & 7;
        const int obase = nl * 768;
        #pragma unroll
        for (int o = 0; o < 12; o++) {
            float acc = bsm[o % 3];
            #pragma unroll
            for (int k = 0; k < 32; k++) acc = fmaf(x[k], ws[o * 32 + k], acc);
            const float v = 1.f / (1.f + __expf(-acc));
            const int a2 = o / 6, c2 = (o / 3) & 1, ch = o % 3;
            ostage[obase + (2 * P + a2) * 48 + (2 * Q + c2) * 3 + ch] = v;
        }
    }
    __syncthreads();

    // coalesced flush: 8 patches * 768 floats contiguous
    float4* gout = reinterpret_cast<float4*>(out + (size_t)blockIdx.x * 6144);
    const float4* so = reinterpret_cast<const float4*>(ostage);
    #pragma unroll
    for (int i = 0; i < 6; i++) gout[tid + i * 256] = so[tid + i * 256];
}

// ---------------------------------------------------------------- host entry
extern "C" void kernel_launch(void* const* d_in, const int* in_sizes, int n_in,
                              void* d_out, int out_size)
{
    const float* in1     = (const float*)d_in[0];
    const float* in2     = (const float*)d_in[1];
    const float* in3     = (const float*)d_in[2];
    const float* dense_w = (const float*)d_in[3];
    const float* dense_b = (const float*)d_in[4];
    const float* w1      = (const float*)d_in[5];
    const float* b1      = (const float*)d_in[6];
    const float* w2      = (const float*)d_in[7];
    const float* b2      = (const float*)d_in[8];
    const float* w3      = (const float*)d_in[9];
    const float* b3      = (const float*)d_in[10];
    float* out           = (float*)d_out;

    __nv_bfloat16 *ain, *x1, *x2, *x3, *wd, *w1b, *w2b;
    cudaGetSymbolAddress((void**)&ain, g_Ain);
    cudaGetSymbolAddress((void**)&x1, g_X1);
    cudaGetSymbolAddress((void**)&x2, g_X2);
    cudaGetSymbolAddress((void**)&x3, g_X3);
    cudaGetSymbolAddress((void**)&wd, g_Wd);
    cudaGetSymbolAddress((void**)&w1b, g_W1);
    cudaGetSymbolAddress((void**)&w2b, g_W2);

    // raise dynamic smem limit (idempotent state setter, capture-safe)
    cudaFuncSetAttribute(mma_gemm<1>, cudaFuncAttributeMaxDynamicSharedMemorySize, SMEM_BYTES);
    cudaFuncSetAttribute(mma_gemm<2>, cudaFuncAttributeMaxDynamicSharedMemorySize, SMEM_BYTES);
    cudaFuncSetAttribute(mma_gemm<3>, cudaFuncAttributeMaxDynamicSharedMemorySize, SMEM_BYTES);

    const int NIN = NP * 512;  // 8388608 per input
    f2bf<<<NIN / 1024, 256>>>(in1, ain, NIN);
    f2bf<<<NIN / 1024, 256>>>(in2, ain + (size_t)NIN, NIN);
    f2bf<<<NIN / 1024, 256>>>(in3, ain + (size_t)2 * NIN, NIN);
    transpose_w<<<dim3(16, 16), dim3(32, 8)>>>(dense_w, wd);
    f2bf<<<(256 * 384) / 1024, 256>>>(w1, w1b, 256 * 384);
    f2bf<<<(128 * 64) / 1024, 256>>>(w2, w2b, 128 * 64);

    // L1: [49152,512] @ Wd^T[512,512]
    mma_gemm<1><<<dim3(512 / BN, L1_M / BM), 256, SMEM_BYTES>>>(
        ain, wd, dense_b, x1, L1_M, 512, 512);
    // L2: [65536,384] @ w1^T[384,256]
    mma_gemm<2><<<dim3(256 / BN, X1_ROWS / BM), 256, SMEM_BYTES>>>(
        x1, w1b, b1, x2, X1_ROWS, 256, 384);
    // L3: [262144,64] @ w2^T[64,128]
    mma_gemm<3><<<dim3(128 / BN, X2_ROWS / BM), 256, SMEM_BYTES>>>(
        x2, w2b, b2, x3, X2_ROWS, 128, 64);
    // L4
    layer4_kernel<<<X3_ROWS / 512, 256>>>(x3, w3, b3, out);
}

// round 8
// speedup vs baseline: 1.0451x; 1.0451x over previous
#include <cuda_runtime.h>
#include <cuda_bf16.h>
#include <math.h>
#include <stdint.h>

// ----------------------------------------------------------------------------
// MultiScaleDecoder, tensor-core version (mma.sync bf16, fp32 accum).
//   prepass: inputs fp32 -> bf16 (one [49152,512] A matrix), weights -> bf16
//   L1: relu(A @ Wd^T)  M=49152 N=512 K=512 -> scatter X1[65536,384] bf16
//   L2: relu(X1 @ w1^T) M=65536 N=256 K=384 -> scatter X2[262144,64] bf16
//   L3: relu(X2 @ w2^T) M=262144 N=128 K=64 -> scatter X3[1048576,32] bf16
//   L4: sigmoid head, smem-staged coalesced output
// GEMM config is the R3-proven one: BK=32, LDP=40, static smem (2 CTAs/SM).
// ----------------------------------------------------------------------------

#define NP 16384
#define L1_M (3 * NP)                 // 49152
#define X1_ROWS (NP * 4)              // 65536
#define X2_ROWS (NP * 16)             // 262144
#define X3_ROWS (NP * 64)             // 1048576

__device__ __align__(256) __nv_bfloat16 g_Ain[(size_t)L1_M * 512];    // 50.3 MB
__device__ __align__(256) __nv_bfloat16 g_X1[(size_t)X1_ROWS * 384];  // 50.3 MB
__device__ __align__(256) __nv_bfloat16 g_X2[(size_t)X2_ROWS * 64];   // 33.6 MB
__device__ __align__(256) __nv_bfloat16 g_X3[(size_t)X3_ROWS * 32];   // 67.1 MB
__device__ __align__(256) __nv_bfloat16 g_Wd[512 * 512];              // [n][k]
__device__ __align__(256) __nv_bfloat16 g_W1[256 * 384];              // [n][k]
__device__ __align__(256) __nv_bfloat16 g_W2[128 * 64];               // [n][k]

// ---------------------------------------------------------------- prepasses
__global__ __launch_bounds__(256) void f2bf(const float* __restrict__ src,
                                            __nv_bfloat16* __restrict__ dst,
                                            int n) {
    int i = (blockIdx.x * 256 + threadIdx.x) * 4;
    if (i < n) {
        float4 v = *reinterpret_cast<const float4*>(src + i);
        *reinterpret_cast<__nv_bfloat162*>(dst + i)     = __floats2bfloat162_rn(v.x, v.y);
        *reinterpret_cast<__nv_bfloat162*>(dst + i + 2) = __floats2bfloat162_rn(v.z, v.w);
    }
}

// dense_w [k=512][n=512] -> g_Wd [n][k] bf16
__global__ void transpose_w(const float* __restrict__ src,
                            __nv_bfloat16* __restrict__ dst) {
    __shared__ float t[32][33];
    int k0 = blockIdx.y * 32, n0 = blockIdx.x * 32;
    int tx = threadIdx.x, ty = threadIdx.y;  // block (32, 8)
    for (int r = ty; r < 32; r += 8) t[r][tx] = src[(k0 + r) * 512 + n0 + tx];
    __syncthreads();
    for (int r = ty; r < 32; r += 8)
        dst[(size_t)(n0 + r) * 512 + k0 + tx] = __float2bfloat16(t[tx][r]);
}

// ---------------------------------------------------------------- mma utils
__device__ __forceinline__ uint32_t smem_u32(const void* p) {
    return (uint32_t)__cvta_generic_to_shared(p);
}
__device__ __forceinline__ void ldsm4(uint32_t& r0, uint32_t& r1, uint32_t& r2,
                                      uint32_t& r3, uint32_t addr) {
    asm volatile("ldmatrix.sync.aligned.m8n8.x4.shared.b16 {%0,%1,%2,%3}, [%4];\n"
                 : "=r"(r0), "=r"(r1), "=r"(r2), "=r"(r3) : "r"(addr));
}
__device__ __forceinline__ void mma16816(float* c, const uint32_t* a,
                                         const uint32_t* b) {
    asm volatile(
        "mma.sync.aligned.m16n8k16.row.col.f32.bf16.bf16.f32 "
        "{%0,%1,%2,%3}, {%4,%5,%6,%7}, {%8,%9}, {%0,%1,%2,%3};\n"
        : "+f"(c[0]), "+f"(c[1]), "+f"(c[2]), "+f"(c[3])
        : "r"(a[0]), "r"(a[1]), "r"(a[2]), "r"(a[3]), "r"(b[0]), "r"(b[1]));
}
__device__ __forceinline__ void cp16(void* sdst, const void* gsrc) {
    asm volatile("cp.async.cg.shared.global [%0], [%1], 16;\n" ::
                 "r"(smem_u32(sdst)), "l"(gsrc));
}

#define BM 128
#define BN 128
#define BK 32
#define LDP 40  // padded smem row (elems): 80B stride -> conflict-free ldmatrix

// ---------------------------------------------------------------- GEMM + scatter
// EPI: 1 = dense->X1 scatter, 2 = deconv1->X2 scatter, 3 = deconv2->X3 scatter
template <int EPI>
__global__ __launch_bounds__(256)
void mma_gemm(const __nv_bfloat16* __restrict__ A,
              const __nv_bfloat16* __restrict__ B,
              const float* __restrict__ bias,
              __nv_bfloat16* __restrict__ Out, int M, int N, int K)
{
    __shared__ __align__(16) __nv_bfloat16 As[2][BM * LDP];
    __shared__ __align__(16) __nv_bfloat16 Bs[2][BN * LDP];

    const int tid = threadIdx.x;
    const int warp = tid >> 5, lane = tid & 31;
    const int row0 = blockIdx.y * BM;
    const int col0 = blockIdx.x * BN;
    const int wm = (warp >> 2) * 64;   // warp tile 64x32
    const int wn = (warp & 3) * 32;

    const int NIT = K / BK;

    auto load_stage = [&](int buf, int ko) {
        #pragma unroll
        for (int c = 0; c < 2; c++) {
            int ch = tid + c * 256;            // 0..511
            int r = ch >> 2, cc = (ch & 3) * 8;
            cp16(&As[buf][r * LDP + cc], &A[(size_t)(row0 + r) * K + ko + cc]);
        }
        #pragma unroll
        for (int c = 0; c < 2; c++) {
            int ch = tid + c * 256;
            int r = ch >> 2, cc = (ch & 3) * 8;
            cp16(&Bs[buf][r * LDP + cc], &B[(size_t)(col0 + r) * K + ko + cc]);
        }
        asm volatile("cp.async.commit_group;\n");
    };

    float acc[4][4][4];
    #pragma unroll
    for (int i = 0; i < 4; i++)
        #pragma unroll
        for (int j = 0; j < 4; j++)
            #pragma unroll
            for (int q = 0; q < 4; q++) acc[i][j][q] = 0.f;

    load_stage(0, 0);

    for (int it = 0; it < NIT; it++) {
        if (it + 1 < NIT) {
            load_stage((it + 1) & 1, (it + 1) * BK);
            asm volatile("cp.async.wait_group 1;\n");
        } else {
            asm volatile("cp.async.wait_group 0;\n");
        }
        __syncthreads();

        const int sb = it & 1;
        #pragma unroll
        for (int ks = 0; ks < 2; ks++) {
            const int k0 = ks * 16;
            uint32_t a[4][4], b[4][2];
            #pragma unroll
            for (int i = 0; i < 4; i++) {
                int r = wm + i * 16 + (lane & 15);
                int kk = k0 + ((lane >> 4) << 3);
                ldsm4(a[i][0], a[i][1], a[i][2], a[i][3],
                      smem_u32(&As[sb][r * LDP + kk]));
            }
            #pragma unroll
            for (int jp = 0; jp < 2; jp++) {
                int rB = wn + jp * 16 + ((lane >> 4) << 3) + (lane & 7);
                int kk = k0 + (((lane >> 3) & 1) << 3);
                ldsm4(b[2 * jp][0], b[2 * jp][1], b[2 * jp + 1][0], b[2 * jp + 1][1],
                      smem_u32(&Bs[sb][rB * LDP + kk]));
            }
            #pragma unroll
            for (int i = 0; i < 4; i++)
                #pragma unroll
                for (int j = 0; j < 4; j++) mma16816(acc[i][j], a[i], b[j]);
        }
        __syncthreads();
    }

    // epilogue: bias + relu + scatter, bf162 pair stores
    auto epi_store = [&](int row, int col, float v0, float v1) {
        float b0, b1;
        if (EPI == 1)      { b0 = bias[col];      b1 = bias[col + 1]; }
        else if (EPI == 2) { b0 = bias[col & 63]; b1 = bias[(col & 63) + 1]; }
        else               { b0 = bias[col & 31]; b1 = bias[(col & 31) + 1]; }
        v0 = fmaxf(v0 + b0, 0.f);
        v1 = fmaxf(v1 + b1, 0.f);
        size_t addr;
        if (EPI == 1) {
            const int pos = col >> 7, kc = col & 127;
            const int s = row >> 14, nl = row & (NP - 1);
            addr = ((size_t)(nl * 4 + pos)) * 384 + s * 128 + kc;
        } else if (EPI == 2) {
            const int a_ = col >> 7, c_ = (col >> 6) & 1, f = col & 63;
            const int nn = row >> 2, ii = (row >> 1) & 1, jj = row & 1;
            addr = ((size_t)(nn * 16 + (2 * ii + a_) * 4 + (2 * jj + c_))) * 64 + f;
        } else {
            const int a_ = col >> 6, c_ = (col >> 5) & 1, f = col & 31;
            const int nn = row >> 4, p = (row >> 2) & 3, q = row & 3;
            addr = ((size_t)(nn * 64 + (2 * p + a_) * 8 + (2 * q + c_))) * 32 + f;
        }
        *reinterpret_cast<__nv_bfloat162*>(&Out[addr]) = __floats2bfloat162_rn(v0, v1);
    };

    #pragma unroll
    for (int i = 0; i < 4; i++) {
        const int mA = row0 + wm + i * 16 + (lane >> 2);
        #pragma unroll
        for (int j = 0; j < 4; j++) {
            const int nA = col0 + wn + j * 8 + 2 * (lane & 3);
            epi_store(mA,     nA, acc[i][j][0], acc[i][j][1]);
            epi_store(mA + 8, nA, acc[i][j][2], acc[i][j][3]);
        }
    }
}

// ----------------------------------------------------------------------------
// Layer 4 standalone, smem-staged coalesced output.
// Block = 8 patches = 512 X3 rows; 256 threads, 2 rows/thread.
// ostage is float4-accessed -> 16B alignment is mandatory.
// ----------------------------------------------------------------------------
__global__ __launch_bounds__(256)
void layer4_kernel(const __nv_bfloat16* __restrict__ X3,
                   const float* __restrict__ w3, const float* __restrict__ b3,
                   float* __restrict__ out)
{
    __shared__ __align__(16) float ostage[6144];   // 24 KB, float4-accessed
    __shared__ float ws[384];
    __shared__ float bsm[3];

    const int tid = threadIdx.x;
    for (int i = tid; i < 384; i += 256) ws[i] = w3[i];
    if (tid < 3) bsm[tid] = b3[tid];
    __syncthreads();

    const int r0 = blockIdx.x * 512;

    #pragma unroll
    for (int h = 0; h < 2; h++) {
        const int rl = tid + h * 256;            // local row 0..511
        const int r  = r0 + rl;
        // coalesced 64B row read
        uint4 xr[4];
        const uint4* xp = reinterpret_cast<const uint4*>(X3 + (size_t)r * 32);
        #pragma unroll
        for (int i = 0; i < 4; i++) xr[i] = xp[i];
        float x[32];
        #pragma unroll
        for (int i = 0; i < 16; i++) {
            __nv_bfloat162 pr = reinterpret_cast<const __nv_bfloat162*>(xr)[i];
            float2 f2 = __bfloat1622float2(pr);
            x[2 * i] = f2.x; x[2 * i + 1] = f2.y;
        }
        const int nl = rl >> 6, P = (rl >> 3) & 7, Q = rl & 7;
        const int obase = nl * 768;
        #pragma unroll
        for (int o = 0; o < 12; o++) {
            float acc = bsm[o % 3];
            #pragma unroll
            for (int k = 0; k < 32; k++) acc = fmaf(x[k], ws[o * 32 + k], acc);
            const float v = 1.f / (1.f + __expf(-acc));
            const int a2 = o / 6, c2 = (o / 3) & 1, ch = o % 3;
            ostage[obase + (2 * P + a2) * 48 + (2 * Q + c2) * 3 + ch] = v;
        }
    }
    __syncthreads();

    // coalesced flush: 8 patches * 768 floats contiguous
    float4* gout = reinterpret_cast<float4*>(out + (size_t)blockIdx.x * 6144);
    const float4* so = reinterpret_cast<const float4*>(ostage);
    #pragma unroll
    for (int i = 0; i < 6; i++) gout[tid + i * 256] = so[tid + i * 256];
}

// ---------------------------------------------------------------- host entry
extern "C" void kernel_launch(void* const* d_in, const int* in_sizes, int n_in,
                              void* d_out, int out_size)
{
    const float* in1     = (const float*)d_in[0];
    const float* in2     = (const float*)d_in[1];
    const float* in3     = (const float*)d_in[2];
    const float* dense_w = (const float*)d_in[3];
    const float* dense_b = (const float*)d_in[4];
    const float* w1      = (const float*)d_in[5];
    const float* b1      = (const float*)d_in[6];
    const float* w2      = (const float*)d_in[7];
    const float* b2      = (const float*)d_in[8];
    const float* w3      = (const float*)d_in[9];
    const float* b3      = (const float*)d_in[10];
    float* out           = (float*)d_out;

    __nv_bfloat16 *ain, *x1, *x2, *x3, *wd, *w1b, *w2b;
    cudaGetSymbolAddress((void**)&ain, g_Ain);
    cudaGetSymbolAddress((void**)&x1, g_X1);
    cudaGetSymbolAddress((void**)&x2, g_X2);
    cudaGetSymbolAddress((void**)&x3, g_X3);
    cudaGetSymbolAddress((void**)&wd, g_Wd);
    cudaGetSymbolAddress((void**)&w1b, g_W1);
    cudaGetSymbolAddress((void**)&w2b, g_W2);

    const int NIN = NP * 512;  // 8388608 per input
    f2bf<<<NIN / 1024, 256>>>(in1, ain, NIN);
    f2bf<<<NIN / 1024, 256>>>(in2, ain + (size_t)NIN, NIN);
    f2bf<<<NIN / 1024, 256>>>(in3, ain + (size_t)2 * NIN, NIN);
    transpose_w<<<dim3(16, 16), dim3(32, 8)>>>(dense_w, wd);
    f2bf<<<(256 * 384) / 1024, 256>>>(w1, w1b, 256 * 384);
    f2bf<<<(128 * 64) / 1024, 256>>>(w2, w2b, 128 * 64);

    // L1: [49152,512] @ Wd^T[512,512]
    mma_gemm<1><<<dim3(512 / BN, L1_M / BM), 256>>>(ain, wd, dense_b, x1,
                                                    L1_M, 512, 512);
    // L2: [65536,384] @ w1^T[384,256]
    mma_gemm<2><<<dim3(256 / BN, X1_ROWS / BM), 256>>>(x1, w1b, b1, x2,
                                                       X1_ROWS, 256, 384);
    // L3: [262144,64] @ w2^T[64,128]
    mma_gemm<3><<<dim3(128 / BN, X2_ROWS / BM), 256>>>(x2, w2b, b2, x3,
                                                       X2_ROWS, 128, 64);
    // L4
    layer4_kernel<<<X3_ROWS / 512, 256>>>(x3, w3, b3, out);
}

// round 10
// speedup vs baseline: 1.1311x; 1.0822x over previous
#include <cuda_runtime.h>
#include <cuda_bf16.h>
#include <math.h>
#include <stdint.h>

// ----------------------------------------------------------------------------
// MultiScaleDecoder, mma.sync bf16 (tcgen05 unavailable: harness targets sm_100).
//   prep_weights: dense_w transpose->bf16, w1/w2 ->bf16 (one launch)
//   L1: relu(A @ Wd^T) M=49152 N=512 K=512, A read DIRECTLY from fp32 inputs
//       (LDG+convert+STS, register double buffer)  -> scatter X1[65536,384]
//   L2: relu(X1 @ w1^T) M=65536 N=256 K=384 -> scatter X2[262144,64]
//   L3: relu(X2 @ w2^T) M=262144 N=128 K=64 -> scatter X3[1048576,32]
//   L4: sigmoid head, smem-staged coalesced output
// ----------------------------------------------------------------------------

#define NP 16384
#define L1_M (3 * NP)                 // 49152
#define X1_ROWS (NP * 4)              // 65536
#define X2_ROWS (NP * 16)             // 262144
#define X3_ROWS (NP * 64)             // 1048576

__device__ __align__(256) __nv_bfloat16 g_X1[(size_t)X1_ROWS * 384];
__device__ __align__(256) __nv_bfloat16 g_X2[(size_t)X2_ROWS * 64];
__device__ __align__(256) __nv_bfloat16 g_X3[(size_t)X3_ROWS * 32];
__device__ __align__(256) __nv_bfloat16 g_Wd[512 * 512];   // [n][k]
__device__ __align__(256) __nv_bfloat16 g_W1[256 * 384];   // [n][k]
__device__ __align__(256) __nv_bfloat16 g_W2[128 * 64];    // [n][k]

// ---------------------------------------------------------------- utils
__device__ __forceinline__ uint32_t smem_u32(const void* p) {
    return (uint32_t)__cvta_generic_to_shared(p);
}
__device__ __forceinline__ void ldsm4(uint32_t& r0, uint32_t& r1, uint32_t& r2,
                                      uint32_t& r3, uint32_t addr) {
    asm volatile("ldmatrix.sync.aligned.m8n8.x4.shared.b16 {%0,%1,%2,%3}, [%4];\n"
                 : "=r"(r0), "=r"(r1), "=r"(r2), "=r"(r3) : "r"(addr));
}
__device__ __forceinline__ void mma16816(float* c, const uint32_t* a,
                                         const uint32_t* b) {
    asm volatile(
        "mma.sync.aligned.m16n8k16.row.col.f32.bf16.bf16.f32 "
        "{%0,%1,%2,%3}, {%4,%5,%6,%7}, {%8,%9}, {%0,%1,%2,%3};\n"
        : "+f"(c[0]), "+f"(c[1]), "+f"(c[2]), "+f"(c[3])
        : "r"(a[0]), "r"(a[1]), "r"(a[2]), "r"(a[3]), "r"(b[0]), "r"(b[1]));
}
__device__ __forceinline__ void cp16(void* sdst, const void* gsrc) {
    asm volatile("cp.async.cg.shared.global [%0], [%1], 16;\n" ::
                 "r"(smem_u32(sdst)), "l"(gsrc));
}

#define BM 128
#define BN 128
#define BK 32
#define LDP 40  // 80B row stride -> conflict-free ldmatrix phases

// ----------------------------------------------------------------------------
// One-launch weight prep:
//  blocks [0,256):   dense_w [k=512][n=512] fp32 -> g_Wd [n][k] bf16 (transpose)
//  blocks [256,352): w1 fp32 -> bf16 (98304 elems)
//  blocks [352,360): w2 fp32 -> bf16 (8192 elems)
// ----------------------------------------------------------------------------
__global__ __launch_bounds__(256)
void prep_weights(const float* __restrict__ dw, const float* __restrict__ w1,
                  const float* __restrict__ w2, __nv_bfloat16* __restrict__ wd,
                  __nv_bfloat16* __restrict__ w1b, __nv_bfloat16* __restrict__ w2b)
{
    const int b = blockIdx.x, tid = threadIdx.x;
    if (b < 256) {
        __shared__ float t[32][33];
        const int n0 = (b & 15) * 32, k0 = (b >> 4) * 32;
        const int tx = tid & 31, ty = tid >> 5;
        for (int r = ty; r < 32; r += 8) t[r][tx] = dw[(k0 + r) * 512 + n0 + tx];
        __syncthreads();
        for (int r = ty; r < 32; r += 8)
            wd[(size_t)(n0 + r) * 512 + k0 + tx] = __float2bfloat16(t[tx][r]);
    } else if (b < 352) {
        const int i = ((b - 256) * 256 + tid) * 4;
        float4 v = *reinterpret_cast<const float4*>(w1 + i);
        *reinterpret_cast<__nv_bfloat162*>(w1b + i)     = __floats2bfloat162_rn(v.x, v.y);
        *reinterpret_cast<__nv_bfloat162*>(w1b + i + 2) = __floats2bfloat162_rn(v.z, v.w);
    } else {
        const int i = ((b - 352) * 256 + tid) * 4;
        float4 v = *reinterpret_cast<const float4*>(w2 + i);
        *reinterpret_cast<__nv_bfloat162*>(w2b + i)     = __floats2bfloat162_rn(v.x, v.y);
        *reinterpret_cast<__nv_bfloat162*>(w2b + i + 2) = __floats2bfloat162_rn(v.z, v.w);
    }
}

// ----------------------------------------------------------------------------
// L1: A loaded straight from fp32 inputs, converted to bf16 in-register,
// stored to smem; B (g_Wd) double-buffered via cp.async. K=512, 16 iters.
// Each 128-row block lies entirely inside one input (128 | 16384).
// ----------------------------------------------------------------------------
__global__ __launch_bounds__(256, 2)
void mma_gemm_l1(const float* __restrict__ A0, const float* __restrict__ A1,
                 const float* __restrict__ A2,
                 const __nv_bfloat16* __restrict__ B,
                 const float* __restrict__ bias,
                 __nv_bfloat16* __restrict__ Out)
{
    constexpr int K = 512;
    __shared__ __align__(16) __nv_bfloat16 As[2][BM * LDP];
    __shared__ __align__(16) __nv_bfloat16 Bs[2][BN * LDP];

    const int tid = threadIdx.x;
    const int warp = tid >> 5, lane = tid & 31;
    const int row0 = blockIdx.y * BM;
    const int col0 = blockIdx.x * BN;
    const int wm = (warp >> 2) * 64;
    const int wn = (warp & 3) * 32;

    const int s = row0 >> 14;                      // which input
    const float* Abase = (s == 0) ? A0 : (s == 1) ? A1 : A2;
    const int lrow0 = row0 & (NP - 1);

    auto ldgA = [&](int ko, float4 (&ra)[2][2]) {
        #pragma unroll
        for (int c = 0; c < 2; c++) {
            const int r = (tid >> 2) + c * 64;
            const int cc = (tid & 3) * 8;
            const float* p = Abase + (size_t)(lrow0 + r) * K + ko + cc;
            ra[c][0] = *reinterpret_cast<const float4*>(p);
            ra[c][1] = *reinterpret_cast<const float4*>(p + 4);
        }
    };
    auto stsA = [&](int buf, const float4 (&ra)[2][2]) {
        #pragma unroll
        for (int c = 0; c < 2; c++) {
            const int r = (tid >> 2) + c * 64;
            const int cc = (tid & 3) * 8;
            uint4 pk;
            __nv_bfloat162 h;
            h = __floats2bfloat162_rn(ra[c][0].x, ra[c][0].y); pk.x = *(const uint32_t*)&h;
            h = __floats2bfloat162_rn(ra[c][0].z, ra[c][0].w); pk.y = *(const uint32_t*)&h;
            h = __floats2bfloat162_rn(ra[c][1].x, ra[c][1].y); pk.z = *(const uint32_t*)&h;
            h = __floats2bfloat162_rn(ra[c][1].z, ra[c][1].w); pk.w = *(const uint32_t*)&h;
            *reinterpret_cast<uint4*>(&As[buf][r * LDP + cc]) = pk;
        }
    };
    auto loadB = [&](int buf, int ko) {
        #pragma unroll
        for (int c = 0; c < 2; c++) {
            const int ch = tid + c * 256;
            const int r = ch >> 2, cc = (ch & 3) * 8;
            cp16(&Bs[buf][r * LDP + cc], &B[(size_t)(col0 + r) * K + ko + cc]);
        }
        asm volatile("cp.async.commit_group;\n");
    };

    float acc[4][4][4];
    #pragma unroll
    for (int i = 0; i < 4; i++)
        #pragma unroll
        for (int j = 0; j < 4; j++)
            #pragma unroll
            for (int q = 0; q < 4; q++) acc[i][j][q] = 0.f;

    float4 ra[2][2];
    ldgA(0, ra);
    loadB(0, 0);

    for (int it = 0; it < 16; it++) {
        const int sb = it & 1;
        stsA(sb, ra);
        if (it + 1 < 16) {
            ldgA((it + 1) * BK, ra);
            loadB((it + 1) & 1, (it + 1) * BK);
            asm volatile("cp.async.wait_group 1;\n");
        } else {
            asm volatile("cp.async.wait_group 0;\n");
        }
        __syncthreads();

        #pragma unroll
        for (int ks = 0; ks < 2; ks++) {
            const int k0 = ks * 16;
            uint32_t a[4][4], b[4][2];
            #pragma unroll
            for (int i = 0; i < 4; i++) {
                int r = wm + i * 16 + (lane & 15);
                int kk = k0 + ((lane >> 4) << 3);
                ldsm4(a[i][0], a[i][1], a[i][2], a[i][3],
                      smem_u32(&As[sb][r * LDP + kk]));
            }
            #pragma unroll
            for (int jp = 0; jp < 2; jp++) {
                int rB = wn + jp * 16 + ((lane >> 4) << 3) + (lane & 7);
                int kk = k0 + (((lane >> 3) & 1) << 3);
                ldsm4(b[2 * jp][0], b[2 * jp][1], b[2 * jp + 1][0], b[2 * jp + 1][1],
                      smem_u32(&Bs[sb][rB * LDP + kk]));
            }
            #pragma unroll
            for (int i = 0; i < 4; i++)
                #pragma unroll
                for (int j = 0; j < 4; j++) mma16816(acc[i][j], a[i], b[j]);
        }
        __syncthreads();
    }

    // epilogue: bias + relu + X1 scatter
    const size_t rowscale = 384;
    #pragma unroll
    for (int i = 0; i < 4; i++) {
        const int mA = row0 + wm + i * 16 + (lane >> 2);
        #pragma unroll
        for (int j = 0; j < 4; j++) {
            const int nA = col0 + wn + j * 8 + 2 * (lane & 3);
            #pragma unroll
            for (int hh = 0; hh < 2; hh++) {
                const int row = mA + hh * 8;
                const float v0 = fmaxf(acc[i][j][2 * hh]     + bias[nA],     0.f);
                const float v1 = fmaxf(acc[i][j][2 * hh + 1] + bias[nA + 1], 0.f);
                const int pos = nA >> 7, kc = nA & 127;
                const int nl = row & (NP - 1);
                const size_t addr = ((size_t)(nl * 4 + pos)) * rowscale + s * 128 + kc;
                *reinterpret_cast<__nv_bfloat162*>(&Out[addr]) =
                    __floats2bfloat162_rn(v0, v1);
            }
        }
    }
}

// ---------------------------------------------------------------- L2/L3 GEMMs
// EPI: 2 = deconv1->X2 scatter, 3 = deconv2->X3 scatter
template <int EPI>
__global__ __launch_bounds__(256)
void mma_gemm(const __nv_bfloat16* __restrict__ A,
              const __nv_bfloat16* __restrict__ B,
              const float* __restrict__ bias,
              __nv_bfloat16* __restrict__ Out, int M, int N, int K)
{
    __shared__ __align__(16) __nv_bfloat16 As[2][BM * LDP];
    __shared__ __align__(16) __nv_bfloat16 Bs[2][BN * LDP];

    const int tid = threadIdx.x;
    const int warp = tid >> 5, lane = tid & 31;
    const int row0 = blockIdx.y * BM;
    const int col0 = blockIdx.x * BN;
    const int wm = (warp >> 2) * 64;
    const int wn = (warp & 3) * 32;
    const int NIT = K / BK;

    auto load_stage = [&](int buf, int ko) {
        #pragma unroll
        for (int c = 0; c < 2; c++) {
            int ch = tid + c * 256;
            int r = ch >> 2, cc = (ch & 3) * 8;
            cp16(&As[buf][r * LDP + cc], &A[(size_t)(row0 + r) * K + ko + cc]);
        }
        #pragma unroll
        for (int c = 0; c < 2; c++) {
            int ch = tid + c * 256;
            int r = ch >> 2, cc = (ch & 3) * 8;
            cp16(&Bs[buf][r * LDP + cc], &B[(size_t)(col0 + r) * K + ko + cc]);
        }
        asm volatile("cp.async.commit_group;\n");
    };

    float acc[4][4][4];
    #pragma unroll
    for (int i = 0; i < 4; i++)
        #pragma unroll
        for (int j = 0; j < 4; j++)
            #pragma unroll
            for (int q = 0; q < 4; q++) acc[i][j][q] = 0.f;

    load_stage(0, 0);

    for (int it = 0; it < NIT; it++) {
        if (it + 1 < NIT) {
            load_stage((it + 1) & 1, (it + 1) * BK);
            asm volatile("cp.async.wait_group 1;\n");
        } else {
            asm volatile("cp.async.wait_group 0;\n");
        }
        __syncthreads();

        const int sb = it & 1;
        #pragma unroll
        for (int ks = 0; ks < 2; ks++) {
            const int k0 = ks * 16;
            uint32_t a[4][4], b[4][2];
            #pragma unroll
            for (int i = 0; i < 4; i++) {
                int r = wm + i * 16 + (lane & 15);
                int kk = k0 + ((lane >> 4) << 3);
                ldsm4(a[i][0], a[i][1], a[i][2], a[i][3],
                      smem_u32(&As[sb][r * LDP + kk]));
            }
            #pragma unroll
            for (int jp = 0; jp < 2; jp++) {
                int rB = wn + jp * 16 + ((lane >> 4) << 3) + (lane & 7);
                int kk = k0 + (((lane >> 3) & 1) << 3);
                ldsm4(b[2 * jp][0], b[2 * jp][1], b[2 * jp + 1][0], b[2 * jp + 1][1],
                      smem_u32(&Bs[sb][rB * LDP + kk]));
            }
            #pragma unroll
            for (int i = 0; i < 4; i++)
                #pragma unroll
                for (int j = 0; j < 4; j++) mma16816(acc[i][j], a[i], b[j]);
        }
        __syncthreads();
    }

    auto epi_store = [&](int row, int col, float v0, float v1) {
        float b0, b1;
        if (EPI == 2) { b0 = bias[col & 63]; b1 = bias[(col & 63) + 1]; }
        else          { b0 = bias[col & 31]; b1 = bias[(col & 31) + 1]; }
        v0 = fmaxf(v0 + b0, 0.f);
        v1 = fmaxf(v1 + b1, 0.f);
        size_t addr;
        if (EPI == 2) {
            const int a_ = col >> 7, c_ = (col >> 6) & 1, f = col & 63;
            const int nn = row >> 2, ii = (row >> 1) & 1, jj = row & 1;
            addr = ((size_t)(nn * 16 + (2 * ii + a_) * 4 + (2 * jj + c_))) * 64 + f;
        } else {
            const int a_ = col >> 6, c_ = (col >> 5) & 1, f = col & 31;
            const int nn = row >> 4, p = (row >> 2) & 3, q = row & 3;
            addr = ((size_t)(nn * 64 + (2 * p + a_) * 8 + (2 * q + c_))) * 32 + f;
        }
        *reinterpret_cast<__nv_bfloat162*>(&Out[addr]) = __floats2bfloat162_rn(v0, v1);
    };

    #pragma unroll
    for (int i = 0; i < 4; i++) {
        const int mA = row0 + wm + i * 16 + (lane >> 2);
        #pragma unroll
        for (int j = 0; j < 4; j++) {
            const int nA = col0 + wn + j * 8 + 2 * (lane & 3);
            epi_store(mA,     nA, acc[i][j][0], acc[i][j][1]);
            epi_store(mA + 8, nA, acc[i][j][2], acc[i][j][3]);
        }
    }
}

// ---------------------------------------------------------------- layer 4
__global__ __launch_bounds__(256)
void layer4_kernel(const __nv_bfloat16* __restrict__ X3,
                   const float* __restrict__ w3, const float* __restrict__ b3,
                   float* __restrict__ out)
{
    __shared__ __align__(16) float ostage[6144];
    __shared__ float ws[384];
    __shared__ float bsm[3];

    const int tid = threadIdx.x;
    for (int i = tid; i < 384; i += 256) ws[i] = w3[i];
    if (tid < 3) bsm[tid] = b3[tid];
    __syncthreads();

    const int r0 = blockIdx.x * 512;

    #pragma unroll
    for (int h = 0; h < 2; h++) {
        const int rl = tid + h * 256;
        const int r  = r0 + rl;
        uint4 xr[4];
        const uint4* xp = reinterpret_cast<const uint4*>(X3 + (size_t)r * 32);
        #pragma unroll
        for (int i = 0; i < 4; i++) xr[i] = xp[i];
        float x[32];
        #pragma unroll
        for (int i = 0; i < 16; i++) {
            __nv_bfloat162 pr = reinterpret_cast<const __nv_bfloat162*>(xr)[i];
            float2 f2 = __bfloat1622float2(pr);
            x[2 * i] = f2.x; x[2 * i + 1] = f2.y;
        }
        const int nl = rl >> 6, P = (rl >> 3) & 7, Q = rl & 7;
        const int obase = nl * 768;
        #pragma unroll
        for (int o = 0; o < 12; o++) {
            float acc = bsm[o % 3];
            #pragma unroll
            for (int k = 0; k < 32; k++) acc = fmaf(x[k], ws[o * 32 + k], acc);
            const float v = 1.f / (1.f + __expf(-acc));
            const int a2 = o / 6, c2 = (o / 3) & 1, ch = o % 3;
            ostage[obase + (2 * P + a2) * 48 + (2 * Q + c2) * 3 + ch] = v;
        }
    }
    __syncthreads();

    float4* gout = reinterpret_cast<float4*>(out + (size_t)blockIdx.x * 6144);
    const float4* so = reinterpret_cast<const float4*>(ostage);
    #pragma unroll
    for (int i = 0; i < 6; i++) gout[tid + i * 256] = so[tid + i * 256];
}

// ---------------------------------------------------------------- host entry
extern "C" void kernel_launch(void* const* d_in, const int* in_sizes, int n_in,
                              void* d_out, int out_size)
{
    const float* in1     = (const float*)d_in[0];
    const float* in2     = (const float*)d_in[1];
    const float* in3     = (const float*)d_in[2];
    const float* dense_w = (const float*)d_in[3];
    const float* dense_b = (const float*)d_in[4];
    const float* w1      = (const float*)d_in[5];
    const float* b1      = (const float*)d_in[6];
    const float* w2      = (const float*)d_in[7];
    const float* b2      = (const float*)d_in[8];
    const float* w3      = (const float*)d_in[9];
    const float* b3      = (const float*)d_in[10];
    float* out           = (float*)d_out;

    __nv_bfloat16 *x1, *x2, *x3, *wd, *w1b, *w2b;
    cudaGetSymbolAddress((void**)&x1, g_X1);
    cudaGetSymbolAddress((void**)&x2, g_X2);
    cudaGetSymbolAddress((void**)&x3, g_X3);
    cudaGetSymbolAddress((void**)&wd, g_Wd);
    cudaGetSymbolAddress((void**)&w1b, g_W1);
    cudaGetSymbolAddress((void**)&w2b, g_W2);

    // one-launch weight prep
    prep_weights<<<360, 256>>>(dense_w, w1, w2, wd, w1b, w2b);

    // L1: direct-from-fp32 A, grid (N/BN, M/BM) = (4, 384)
    mma_gemm_l1<<<dim3(512 / BN, L1_M / BM), 256>>>(in1, in2, in3, wd,
                                                    dense_b, x1);
    // L2: [65536,384] @ w1^T[384,256]
    mma_gemm<2><<<dim3(256 / BN, X1_ROWS / BM), 256>>>(x1, w1b, b1, x2,
                                                       X1_ROWS, 256, 384);
    // L3: [262144,64] @ w2^T[64,128]
    mma_gemm<3><<<dim3(128 / BN, X2_ROWS / BM), 256>>>(x2, w2b, b2, x3,
                                                       X2_ROWS, 128, 64);
    // L4
    layer4_kernel<<<X3_ROWS / 512, 256>>>(x3, w3, b3, out);
}